// round 12
// baseline (speedup 1.0000x reference)
#include <cuda_runtime.h>
#include <cuda_bf16.h>
#include <math.h>
#include <stdint.h>

typedef unsigned long long ull;

#define NBLK 128
#define NSTEP 50
#define NOUT 50257

// ---------------- device scratch (no allocs allowed) ----------------
__device__ float g_X[64 * 1024];      // padded inputs (rows 50..63 zero)
__device__ float g_Gin[50 * 4096];    // W_ih @ x_t + b_ih + b_hh
__device__ float g_HS[64 * 1024];     // h_t history (rows 50..63 zero)
__device__ float g_h[2][1024];        // double-buffered hidden state
__device__ unsigned g_arrive;         // cumulative grid-barrier counter
__device__ __align__(16) unsigned g_Ah[64 * 512];  // A bf16-hi pairs (X or HS)
__device__ __align__(16) unsigned g_Al[64 * 512];  // A bf16-lo pairs

// ---------------- helpers ----------------
__device__ __forceinline__ ull pack2(float x, float y) {
    ull r;
    asm("mov.b64 %0, {%1, %2};" : "=l"(r) : "f"(x), "f"(y));
    return r;
}
__device__ __forceinline__ void ffma2(ull& d, ull a, ull b) {
    asm("fma.rn.f32x2 %0, %1, %2, %0;" : "+l"(d) : "l"(a), "l"(b));
}
__device__ __forceinline__ ull addf2(ull a, ull b) {
    ull r;
    asm("add.rn.f32x2 %0, %1, %2;" : "=l"(r) : "l"(a), "l"(b));
    return r;
}
__device__ __forceinline__ float sum2(ull a) {
    float2 v = *(float2*)&a;
    return v.x + v.y;
}
__device__ __forceinline__ void red_release_add1(unsigned* p) {
    asm volatile("red.release.gpu.global.add.u32 [%0], 1;" :: "l"(p) : "memory");
}
__device__ __forceinline__ unsigned ld_acquire(const unsigned* p) {
    unsigned v;
    asm volatile("ld.acquire.gpu.global.u32 %0, [%1];" : "=r"(v) : "l"(p) : "memory");
    return v;
}

// bf16 hi/lo split of a float pair, packed little-endian (x=low half)
__device__ __forceinline__ void cvt_pair(float x, float y, unsigned& hi, unsigned& lo) {
    __nv_bfloat162 h = __floats2bfloat162_rn(x, y);
    float rx = x - __bfloat162float(h.x);
    float ry = y - __bfloat162float(h.y);
    __nv_bfloat162 l = __floats2bfloat162_rn(rx, ry);
    hi = *(unsigned*)&h;
    lo = *(unsigned*)&l;
}

// mma.sync m16n8k16 bf16 (baseline PTX, works on compute_100)
__device__ __forceinline__ void mma_bf16(float* d, const unsigned* a, const unsigned* b) {
    asm volatile(
        "mma.sync.aligned.m16n8k16.row.col.f32.bf16.bf16.f32 "
        "{%0,%1,%2,%3}, {%4,%5,%6,%7}, {%8,%9}, {%0,%1,%2,%3};"
        : "+f"(d[0]), "+f"(d[1]), "+f"(d[2]), "+f"(d[3])
        : "r"(a[0]), "r"(a[1]), "r"(a[2]), "r"(a[3]), "r"(b[0]), "r"(b[1]));
}

// ---------------- prep: gather X rows, zero pads, init state, reset barrier ----------------
__global__ void prep_kernel(const int* __restrict__ sent,
                            const float* __restrict__ emb,
                            const float* __restrict__ h0) {
    int b = blockIdx.x;
    int tid = threadIdx.x;  // 256 threads, float4 each -> 1024 floats
    if (b < 64) {
        float4* dst = (float4*)(g_X + (size_t)b * 1024);
        if (b < 50) {
            int row = (b == 0) ? 1 : sent[b - 1];  // START_ID = 1
            const float4* src = (const float4*)(emb + (size_t)row * 1024);
            dst[tid] = src[tid];
        } else {
            float4 z = make_float4(0.f, 0.f, 0.f, 0.f);
            dst[tid] = z;
            ((float4*)(g_HS + (size_t)b * 1024))[tid] = z;  // zero MMA pad rows
        }
    } else {
        ((float4*)g_h[0])[tid] = ((const float4*)h0)[tid];
        if (tid == 0) g_arrive = 0u;
    }
}

// ---------------- split a fp32 [64][1024] matrix into packed bf16 hi/lo ----------------
__global__ void cvt_split_kernel(const float* __restrict__ src) {
    int i = blockIdx.x * 256 + threadIdx.x;  // over 32768 float2 pairs
    float2 v = ((const float2*)src)[i];
    unsigned hi, lo;
    cvt_pair(v.x, v.y, hi, lo);
    g_Ah[i] = hi;
    g_Al[i] = lo;
}

// ---------------- bf16x3 tensor-core GEMM: C[m][n] = A[m][:]·W[n][:] + bias ----------------
// A: precomputed hi/lo packed bf16 pairs [64][512]. W: [N][1024] fp32 row-major.
// CTA: 256 threads (8 warps), BM=64, BN=128; warp covers M64 x N16 (2 n8 tiles).
// K=1024 in 64 BK=16 steps. Double-buffered smem (1 sync/iter) + 2-deep LDG prefetch.
// 3-term bf16 split: D += Ah*Bh + Ah*Bl + Al*Bh.
__global__ __launch_bounds__(256) void gemm_bf16x3(
    const unsigned* __restrict__ Ah, const unsigned* __restrict__ Al,
    const float* __restrict__ W, float* __restrict__ C,
    const float* __restrict__ bias1, const float* __restrict__ bias2,
    int N, int ldc) {
    __shared__ unsigned sAh[2][64][12];
    __shared__ unsigned sAl[2][64][12];
    __shared__ unsigned sBh[2][128][12];
    __shared__ unsigned sBl[2][128][12];

    const int tid = threadIdx.x;
    const int wid = tid >> 5;   // 0..7
    const int lane = tid & 31;
    const int l4 = lane >> 2;   // group 0..7
    const int lq = lane & 3;    // thread-in-group
    const int n_block = blockIdx.x * 128;

    float d[4][2][4];
#pragma unroll
    for (int mt = 0; mt < 4; mt++)
#pragma unroll
        for (int nt = 0; nt < 2; nt++)
#pragma unroll
            for (int q = 0; q < 4; q++) d[mt][nt][q] = 0.f;

    // ---- fill mappings ----
    // A: j = tid&127 -> row j>>1, seg (j&1)*4; matrix sel = tid>>7 (0=hi, 1=lo)
    const int aj = tid & 127;
    const int arow = aj >> 1;
    const int aseg = (aj & 1) * 4;
    const bool aLo = (tid >> 7) != 0;
    const unsigned* Asrc = aLo ? Al : Ah;
    // B: row = tid>>1 (0..127), q2 = (tid&1)*2  -> float4 s in {0,1}
    const int brow = tid >> 1;
    const int bq2 = (tid & 1) * 2;
    const int bgn = n_block + brow;
    const bool bok = (bgn < N);
    const float* Bsrc = W + (size_t)bgn * 1024;

    // ---- 2-deep prefetch slots ----
    uint4 pa[2];
    float4 pb[2][2];

    // prologue: tile0 -> slot0 -> buf0 ; tile1 -> slot1
    pa[0] = *(const uint4*)(Asrc + (size_t)arow * 512 + 0 * 8 + aseg);
#pragma unroll
    for (int s = 0; s < 2; s++) {
        pb[0][s] = make_float4(0.f, 0.f, 0.f, 0.f);
        if (bok) pb[0][s] = *(const float4*)(Bsrc + 0 + (bq2 + s) * 4);
    }
    {
        // STS tile0 -> buffer0
        if (aLo) *(uint4*)&sAl[0][arow][aseg] = pa[0];
        else *(uint4*)&sAh[0][arow][aseg] = pa[0];
#pragma unroll
        for (int s = 0; s < 2; s++) {
            unsigned h0, l0, h1, l1;
            cvt_pair(pb[0][s].x, pb[0][s].y, h0, l0);
            cvt_pair(pb[0][s].z, pb[0][s].w, h1, l1);
            int q = bq2 + s;
            sBh[0][brow][q * 2] = h0;
            sBh[0][brow][q * 2 + 1] = h1;
            sBl[0][brow][q * 2] = l0;
            sBl[0][brow][q * 2 + 1] = l1;
        }
    }
    pa[1] = *(const uint4*)(Asrc + (size_t)arow * 512 + 1 * 8 + aseg);
#pragma unroll
    for (int s = 0; s < 2; s++) {
        pb[1][s] = make_float4(0.f, 0.f, 0.f, 0.f);
        if (bok) pb[1][s] = *(const float4*)(Bsrc + 16 + (bq2 + s) * 4);
    }
    __syncthreads();

    for (int kt = 0; kt < 64; kt++) {
        const int buf = kt & 1;
        const int slot = kt & 1;       // slot freed by STS below (was tile kt)
        // LDG tile kt+2 into freed slot (2-iteration latency cover)
        if (kt + 2 < 64) {
            const int kp = (kt + 2) * 16;
            pa[slot] = *(const uint4*)(Asrc + (size_t)arow * 512 + (kt + 2) * 8 + aseg);
#pragma unroll
            for (int s = 0; s < 2; s++) {
                pb[slot][s] = make_float4(0.f, 0.f, 0.f, 0.f);
                if (bok) pb[slot][s] = *(const float4*)(Bsrc + kp + (bq2 + s) * 4);
            }
        }

        // ---- fragments + mma on current buffer ----
        {
            unsigned bh[2][2], bl[2][2];
#pragma unroll
            for (int nt = 0; nt < 2; nt++) {
                int n = wid * 16 + nt * 8 + l4;
                bh[nt][0] = sBh[buf][n][lq];
                bh[nt][1] = sBh[buf][n][lq + 4];
                bl[nt][0] = sBl[buf][n][lq];
                bl[nt][1] = sBl[buf][n][lq + 4];
            }
#pragma unroll
            for (int mt = 0; mt < 4; mt++) {
                int r0 = mt * 16 + l4;
                unsigned ah[4], al[4];
                ah[0] = sAh[buf][r0][lq];
                ah[1] = sAh[buf][r0 + 8][lq];
                ah[2] = sAh[buf][r0][lq + 4];
                ah[3] = sAh[buf][r0 + 8][lq + 4];
                al[0] = sAl[buf][r0][lq];
                al[1] = sAl[buf][r0 + 8][lq];
                al[2] = sAl[buf][r0][lq + 4];
                al[3] = sAl[buf][r0 + 8][lq + 4];
#pragma unroll
                for (int nt = 0; nt < 2; nt++) {
                    mma_bf16(d[mt][nt], ah, bh[nt]);
                    mma_bf16(d[mt][nt], ah, bl[nt]);
                    mma_bf16(d[mt][nt], al, bh[nt]);
                }
            }
        }

        // ---- cvt + STS tile kt+1 (regs loaded 1 iter ago) into other buffer ----
        if (kt + 1 < 64) {
            const int ns = (kt + 1) & 1;
            if (aLo) *(uint4*)&sAl[ns][arow][aseg] = pa[ns];
            else *(uint4*)&sAh[ns][arow][aseg] = pa[ns];
#pragma unroll
            for (int s = 0; s < 2; s++) {
                unsigned h0, l0, h1, l1;
                cvt_pair(pb[ns][s].x, pb[ns][s].y, h0, l0);
                cvt_pair(pb[ns][s].z, pb[ns][s].w, h1, l1);
                int q = bq2 + s;
                sBh[ns][brow][q * 2] = h0;
                sBh[ns][brow][q * 2 + 1] = h1;
                sBl[ns][brow][q * 2] = l0;
                sBl[ns][brow][q * 2 + 1] = l1;
            }
        }
        __syncthreads();
    }

    // epilogue: d[mt][nt] -> rows m<50, cols<N, + bias
#pragma unroll
    for (int mt = 0; mt < 4; mt++) {
        int row0 = mt * 16 + l4;
#pragma unroll
        for (int nt = 0; nt < 2; nt++) {
            int col0 = n_block + wid * 16 + nt * 8 + lq * 2;
#pragma unroll
            for (int half = 0; half < 2; half++) {
                int row = row0 + half * 8;
                if (row < 50) {
                    float* crow = C + (size_t)row * ldc;
                    if (col0 < N) {
                        float bv = bias1[col0] + (bias2 ? bias2[col0] : 0.f);
                        crow[col0] = d[mt][nt][half * 2 + 0] + bv;
                    }
                    if (col0 + 1 < N) {
                        float bv = bias1[col0 + 1] + (bias2 ? bias2[col0 + 1] : 0.f);
                        crow[col0 + 1] = d[mt][nt][half * 2 + 1] + bv;
                    }
                }
            }
        }
    }
}

// ---------------- persistent LSTM (R8-proven; 4-acc micro-tweak only) ----------------
__global__ __launch_bounds__(256, 1) void lstm_persistent(
    const float* __restrict__ Whh,      // [4096][1024]
    const float* __restrict__ gin_all,  // [50][4096]
    const float* __restrict__ c0) {     // [1024]
    const int b = blockIdx.x;
    const int tid = threadIdx.x;
    const int w = tid >> 5;              // warp -> unit b*8+w
    const int lane = tid & 31;
    const int r = lane >> 3;             // gate 0..3
    const int c = lane & 7;              // chunk 0..7
    const int u = b * 8 + w;
    const int grow = r * 1024 + u;

    __shared__ __align__(16) ull h_q[512];
    __shared__ float sGin[NSTEP][4][8];

    if (tid < 200) {
        int t = tid >> 2, g = tid & 3;
        const float4* src = (const float4*)(gin_all + (size_t)t * 4096 + g * 1024 + b * 8);
        ((float4*)&sGin[t][g][0])[0] = src[0];
        ((float4*)&sGin[t][g][0])[1] = src[1];
    }
    float cc = 0.f;
    if (lane == 0) cc = c0[u];

    ull Wq[64];
    const float4* wp = (const float4*)(Whh + (size_t)grow * 1024);
#pragma unroll
    for (int it = 0; it < 32; it++) {
        float4 w4 = wp[it * 8 + c];
        Wq[2 * it + 0] = pack2(w4.x, w4.y);
        Wq[2 * it + 1] = pack2(w4.z, w4.w);
    }
    __syncthreads();

    for (int t = 0; t < NSTEP; t++) {
        {
            float4 hv = ((const float4*)g_h[t & 1])[tid];
            ulonglong2 hq;
            hq.x = pack2(hv.x, hv.y);
            hq.y = pack2(hv.z, hv.w);
            *((ulonglong2*)&h_q[2 * tid]) = hq;
        }
        __syncthreads();

        ull a0 = 0, a1 = 0, a2 = 0, a3 = 0;
#pragma unroll
        for (int it = 0; it < 32; it++) {
            ulonglong2 hq = *(const ulonglong2*)&h_q[it * 16 + c * 2];
            if (it & 1) {
                ffma2(a2, Wq[2 * it + 0], hq.x);
                ffma2(a3, Wq[2 * it + 1], hq.y);
            } else {
                ffma2(a0, Wq[2 * it + 0], hq.x);
                ffma2(a1, Wq[2 * it + 1], hq.y);
            }
        }
        float sum = sum2(addf2(addf2(a0, a2), addf2(a1, a3)));
        sum += __shfl_xor_sync(0xFFFFFFFFu, sum, 1);
        sum += __shfl_xor_sync(0xFFFFFFFFu, sum, 2);
        sum += __shfl_xor_sync(0xFFFFFFFFu, sum, 4);
        sum += sGin[t][r][w];

        float vi = __shfl_sync(0xFFFFFFFFu, sum, 0);
        float vf = __shfl_sync(0xFFFFFFFFu, sum, 8);
        float vg = __shfl_sync(0xFFFFFFFFu, sum, 16);
        float vo = __shfl_sync(0xFFFFFFFFu, sum, 24);

        if (lane == 0) {
            float ig = __fdividef(1.f, 1.f + __expf(-vi));
            float fg = __fdividef(1.f, 1.f + __expf(-vf));
            float gg = 1.f - __fdividef(2.f, __expf(2.f * vg) + 1.f);
            float og = __fdividef(1.f, 1.f + __expf(-vo));
            float cn = fg * cc + ig * gg;
            cc = cn;
            float hn = og * (1.f - __fdividef(2.f, __expf(2.f * cn) + 1.f));
            g_h[(t + 1) & 1][u] = hn;
            g_HS[(size_t)t * 1024 + u] = hn;
        }
        __syncthreads();

        if (tid == 0) {
            red_release_add1(&g_arrive);
            const unsigned target = (unsigned)NBLK * (unsigned)(t + 1);
            while (ld_acquire(&g_arrive) < target) {}
        }
        __syncthreads();
    }
}

// ---------------- launch ----------------
extern "C" void kernel_launch(void* const* d_in, const int* in_sizes, int n_in,
                              void* d_out, int out_size) {
    const int* sent = (const int*)d_in[0];
    const float* h0 = (const float*)d_in[1];
    const float* c0 = (const float*)d_in[2];
    const float* emb = (const float*)d_in[3];
    const float* Wih = (const float*)d_in[4];
    const float* Whh = (const float*)d_in[5];
    const float* bih = (const float*)d_in[6];
    const float* bhh = (const float*)d_in[7];
    const float* Wout = (const float*)d_in[8];
    const float* bout = (const float*)d_in[9];
    float* out = (float*)d_out;

    float* gX;
    float* gGin;
    float* gHS;
    unsigned* gAh;
    unsigned* gAl;
    cudaGetSymbolAddress((void**)&gX, g_X);
    cudaGetSymbolAddress((void**)&gGin, g_Gin);
    cudaGetSymbolAddress((void**)&gHS, g_HS);
    cudaGetSymbolAddress((void**)&gAh, g_Ah);
    cudaGetSymbolAddress((void**)&gAl, g_Al);

    // 1) gather inputs + init state + reset barrier
    prep_kernel<<<65, 256>>>(sent, emb, h0);

    // 2) input projection: Gin = X @ W_ih^T + (b_ih + b_hh)
    cvt_split_kernel<<<128, 256>>>(gX);
    gemm_bf16x3<<<4096 / 128, 256>>>(gAh, gAl, Wih, gGin, bih, bhh, 4096, 4096);

    // 3) persistent recurrence (register-resident W_hh, counter barrier)
    lstm_persistent<<<NBLK, 256>>>(Whh, gGin, c0);

    // 4) output projection: logits = HS @ W_out^T + b_out
    cvt_split_kernel<<<128, 256>>>(gHS);
    gemm_bf16x3<<<(NOUT + 127) / 128, 256>>>(gAh, gAl, Wout, out, bout, nullptr,
                                             NOUT, NOUT);
}

// round 13
// speedup vs baseline: 1.4430x; 1.4430x over previous
#include <cuda_runtime.h>
#include <cuda_bf16.h>
#include <math.h>
#include <stdint.h>

typedef unsigned long long ull;

#define NBLK 128
#define NSTEP 50
#define NOUT 50257

// ---------------- device scratch (no allocs allowed) ----------------
__device__ float g_X[64 * 1024];      // padded inputs (rows 50..63 zero)
__device__ float g_Gin[50 * 4096];    // W_ih @ x_t + b_ih + b_hh
__device__ float g_HS[64 * 1024];     // h_t history (rows 50..63 zero)
__device__ float g_h[2][1024];        // double-buffered hidden state
__device__ unsigned g_arrive;         // cumulative grid-barrier counter
__device__ __align__(16) unsigned g_Ah[64 * 512];  // A bf16-hi pairs (X or HS)
__device__ __align__(16) unsigned g_Al[64 * 512];  // A bf16-lo pairs

// ---------------- helpers ----------------
__device__ __forceinline__ ull pack2(float x, float y) {
    ull r;
    asm("mov.b64 %0, {%1, %2};" : "=l"(r) : "f"(x), "f"(y));
    return r;
}
__device__ __forceinline__ void ffma2(ull& d, ull a, ull b) {
    asm("fma.rn.f32x2 %0, %1, %2, %0;" : "+l"(d) : "l"(a), "l"(b));
}
__device__ __forceinline__ float sum2(ull a) {
    float2 v = *(float2*)&a;
    return v.x + v.y;
}
__device__ __forceinline__ void red_release_add1(unsigned* p) {
    asm volatile("red.release.gpu.global.add.u32 [%0], 1;" :: "l"(p) : "memory");
}
__device__ __forceinline__ unsigned ld_acquire(const unsigned* p) {
    unsigned v;
    asm volatile("ld.acquire.gpu.global.u32 %0, [%1];" : "=r"(v) : "l"(p) : "memory");
    return v;
}

// bf16 hi/lo split of a float pair, packed little-endian (x=low half)
__device__ __forceinline__ void cvt_pair(float x, float y, unsigned& hi, unsigned& lo) {
    __nv_bfloat162 h = __floats2bfloat162_rn(x, y);
    float rx = x - __bfloat162float(h.x);
    float ry = y - __bfloat162float(h.y);
    __nv_bfloat162 l = __floats2bfloat162_rn(rx, ry);
    hi = *(unsigned*)&h;
    lo = *(unsigned*)&l;
}

// mma.sync m16n8k16 bf16 (baseline PTX, works on compute_100)
__device__ __forceinline__ void mma_bf16(float* d, const unsigned* a, const unsigned* b) {
    asm volatile(
        "mma.sync.aligned.m16n8k16.row.col.f32.bf16.bf16.f32 "
        "{%0,%1,%2,%3}, {%4,%5,%6,%7}, {%8,%9}, {%0,%1,%2,%3};"
        : "+f"(d[0]), "+f"(d[1]), "+f"(d[2]), "+f"(d[3])
        : "r"(a[0]), "r"(a[1]), "r"(a[2]), "r"(a[3]), "r"(b[0]), "r"(b[1]));
}

// ---------------- prep: gather X rows, zero pads, init state, reset barrier ----------------
__global__ void prep_kernel(const int* __restrict__ sent,
                            const float* __restrict__ emb,
                            const float* __restrict__ h0) {
    int b = blockIdx.x;
    int tid = threadIdx.x;  // 256 threads, float4 each -> 1024 floats
    if (b < 64) {
        float4* dst = (float4*)(g_X + (size_t)b * 1024);
        if (b < 50) {
            int row = (b == 0) ? 1 : sent[b - 1];  // START_ID = 1
            const float4* src = (const float4*)(emb + (size_t)row * 1024);
            dst[tid] = src[tid];
        } else {
            float4 z = make_float4(0.f, 0.f, 0.f, 0.f);
            dst[tid] = z;
            ((float4*)(g_HS + (size_t)b * 1024))[tid] = z;  // zero MMA pad rows
        }
    } else {
        ((float4*)g_h[0])[tid] = ((const float4*)h0)[tid];
        if (tid == 0) g_arrive = 0u;
    }
}

// ---------------- split a fp32 [64][1024] matrix into packed bf16 hi/lo ----------------
__global__ void cvt_split_kernel(const float* __restrict__ src) {
    int i = blockIdx.x * 256 + threadIdx.x;  // over 32768 float2 pairs
    float2 v = ((const float2*)src)[i];
    unsigned hi, lo;
    cvt_pair(v.x, v.y, hi, lo);
    g_Ah[i] = hi;
    g_Al[i] = lo;
}

// ---------------- bf16x3 tensor-core GEMM: C[m][n] = A[m][:]·W[n][:] + bias ----------------
// EXACT R11 structure (proven 266us) with ONE change: double-buffered smem,
// single __syncthreads per k-iteration.
// A: precomputed hi/lo packed bf16 pairs [64][512]. W: [N][1024] fp32 row-major.
// CTA: BM=64, BN=NT*32, 4 warps; warp = full M x NT*8 N. BK=16 steps, K=1024.
// 3-term bf16 split: D += Ah*Bh + Ah*Bl + Al*Bh.
template <int NT>
__global__ __launch_bounds__(128) void gemm_bf16x3(
    const unsigned* __restrict__ Ah, const unsigned* __restrict__ Al,
    const float* __restrict__ W, float* __restrict__ C,
    const float* __restrict__ bias1, const float* __restrict__ bias2,
    int N, int ldc) {
    constexpr int BN = NT * 32;
    __shared__ unsigned sAh[2][64][12];
    __shared__ unsigned sAl[2][64][12];
    __shared__ unsigned sBh[2][BN][12];
    __shared__ unsigned sBl[2][BN][12];

    const int tid = threadIdx.x;
    const int wid = tid >> 5;
    const int lane = tid & 31;
    const int l4 = lane >> 2;   // group 0..7
    const int lq = lane & 3;    // thread-in-group
    const int n_block = blockIdx.x * BN;

    float d[4][NT][4];
#pragma unroll
    for (int mt = 0; mt < 4; mt++)
#pragma unroll
        for (int nt = 0; nt < NT; nt++)
#pragma unroll
            for (int q = 0; q < 4; q++) d[mt][nt][q] = 0.f;

    // fill mappings (identical to R11)
    const int ar = tid >> 1;              // A row 0..63
    const int aseg = (tid & 1) * 4;       // word segment {0,4}

    // prologue: LDG tile0 -> STS buf0 ; LDG tile1 -> regs
    uint4 pah = *(const uint4*)(Ah + (size_t)ar * 512 + aseg);
    uint4 pal = *(const uint4*)(Al + (size_t)ar * 512 + aseg);
    float4 pb[NT];
#pragma unroll
    for (int s = 0; s < NT; s++) {
        int i = s * 128 + tid;
        int row = i >> 2, q = i & 3;
        int gn = n_block + row;
        pb[s] = make_float4(0.f, 0.f, 0.f, 0.f);
        if (gn < N) pb[s] = *(const float4*)(W + (size_t)gn * 1024 + q * 4);
    }
    {
        *(uint4*)&sAh[0][ar][aseg] = pah;
        *(uint4*)&sAl[0][ar][aseg] = pal;
#pragma unroll
        for (int s = 0; s < NT; s++) {
            int i = s * 128 + tid;
            int row = i >> 2, q = i & 3;
            unsigned h0, l0, h1, l1;
            cvt_pair(pb[s].x, pb[s].y, h0, l0);
            cvt_pair(pb[s].z, pb[s].w, h1, l1);
            sBh[0][row][q * 2] = h0;
            sBh[0][row][q * 2 + 1] = h1;
            sBl[0][row][q * 2] = l0;
            sBl[0][row][q * 2 + 1] = l1;
        }
    }
    __syncthreads();

    for (int kt = 0; kt < 64; kt++) {
        const int buf = kt & 1;
        // ---- prefetch next tile into regs (covered by mma below) ----
        if (kt + 1 < 64) {
            const int kp = (kt + 1) * 16;
            pah = *(const uint4*)(Ah + (size_t)ar * 512 + (kt + 1) * 8 + aseg);
            pal = *(const uint4*)(Al + (size_t)ar * 512 + (kt + 1) * 8 + aseg);
#pragma unroll
            for (int s = 0; s < NT; s++) {
                int i = s * 128 + tid;
                int row = i >> 2, q = i & 3;
                int gn = n_block + row;
                pb[s] = make_float4(0.f, 0.f, 0.f, 0.f);
                if (gn < N) pb[s] = *(const float4*)(W + (size_t)gn * 1024 + kp + q * 4);
            }
        }

        // ---- fragments + mma on current buffer ----
        {
            unsigned bh[NT][2], bl[NT][2];
#pragma unroll
            for (int nt = 0; nt < NT; nt++) {
                int n = wid * (NT * 8) + nt * 8 + l4;
                bh[nt][0] = sBh[buf][n][lq];
                bh[nt][1] = sBh[buf][n][lq + 4];
                bl[nt][0] = sBl[buf][n][lq];
                bl[nt][1] = sBl[buf][n][lq + 4];
            }
#pragma unroll
            for (int mt = 0; mt < 4; mt++) {
                int r0 = mt * 16 + l4;
                unsigned ah[4], al[4];
                ah[0] = sAh[buf][r0][lq];
                ah[1] = sAh[buf][r0 + 8][lq];
                ah[2] = sAh[buf][r0][lq + 4];
                ah[3] = sAh[buf][r0 + 8][lq + 4];
                al[0] = sAl[buf][r0][lq];
                al[1] = sAl[buf][r0 + 8][lq];
                al[2] = sAl[buf][r0][lq + 4];
                al[3] = sAl[buf][r0 + 8][lq + 4];
#pragma unroll
                for (int nt = 0; nt < NT; nt++) {
                    mma_bf16(d[mt][nt], ah, bh[nt]);
                    mma_bf16(d[mt][nt], ah, bl[nt]);
                    mma_bf16(d[mt][nt], al, bh[nt]);
                }
            }
        }

        // ---- cvt + STS next tile into OTHER buffer (no extra sync needed) ----
        if (kt + 1 < 64) {
            const int nb = buf ^ 1;
            *(uint4*)&sAh[nb][ar][aseg] = pah;
            *(uint4*)&sAl[nb][ar][aseg] = pal;
#pragma unroll
            for (int s = 0; s < NT; s++) {
                int i = s * 128 + tid;
                int row = i >> 2, q = i & 3;
                unsigned h0, l0, h1, l1;
                cvt_pair(pb[s].x, pb[s].y, h0, l0);
                cvt_pair(pb[s].z, pb[s].w, h1, l1);
                sBh[nb][row][q * 2] = h0;
                sBh[nb][row][q * 2 + 1] = h1;
                sBl[nb][row][q * 2] = l0;
                sBl[nb][row][q * 2 + 1] = l1;
            }
        }
        __syncthreads();
    }

    // epilogue: d[mt][nt] -> rows m<50, cols<N, + bias
#pragma unroll
    for (int mt = 0; mt < 4; mt++) {
        int row0 = mt * 16 + l4;
#pragma unroll
        for (int nt = 0; nt < NT; nt++) {
            int col0 = n_block + wid * (NT * 8) + nt * 8 + lq * 2;
#pragma unroll
            for (int half = 0; half < 2; half++) {
                int row = row0 + half * 8;
                if (row < 50) {
                    float* crow = C + (size_t)row * ldc;
                    if (col0 < N) {
                        float bv = bias1[col0] + (bias2 ? bias2[col0] : 0.f);
                        crow[col0] = d[mt][nt][half * 2 + 0] + bv;
                    }
                    if (col0 + 1 < N) {
                        float bv = bias1[col0 + 1] + (bias2 ? bias2[col0 + 1] : 0.f);
                        crow[col0 + 1] = d[mt][nt][half * 2 + 1] + bv;
                    }
                }
            }
        }
    }
}

// ---------------- persistent LSTM (R11-proven, unchanged) ----------------
__global__ __launch_bounds__(256, 1) void lstm_persistent(
    const float* __restrict__ Whh,      // [4096][1024]
    const float* __restrict__ gin_all,  // [50][4096]
    const float* __restrict__ c0) {     // [1024]
    const int b = blockIdx.x;
    const int tid = threadIdx.x;
    const int w = tid >> 5;              // warp -> unit b*8+w
    const int lane = tid & 31;
    const int r = lane >> 3;             // gate 0..3
    const int c = lane & 7;              // chunk 0..7
    const int u = b * 8 + w;
    const int grow = r * 1024 + u;

    __shared__ __align__(16) ull h_q[512];
    __shared__ float sGin[NSTEP][4][8];

    if (tid < 200) {
        int t = tid >> 2, g = tid & 3;
        const float4* src = (const float4*)(gin_all + (size_t)t * 4096 + g * 1024 + b * 8);
        ((float4*)&sGin[t][g][0])[0] = src[0];
        ((float4*)&sGin[t][g][0])[1] = src[1];
    }
    float cc = 0.f;
    if (lane == 0) cc = c0[u];

    ull Wq[64];
    const float4* wp = (const float4*)(Whh + (size_t)grow * 1024);
#pragma unroll
    for (int it = 0; it < 32; it++) {
        float4 w4 = wp[it * 8 + c];
        Wq[2 * it + 0] = pack2(w4.x, w4.y);
        Wq[2 * it + 1] = pack2(w4.z, w4.w);
    }
    __syncthreads();

    for (int t = 0; t < NSTEP; t++) {
        {
            float4 hv = ((const float4*)g_h[t & 1])[tid];
            ulonglong2 hq;
            hq.x = pack2(hv.x, hv.y);
            hq.y = pack2(hv.z, hv.w);
            *((ulonglong2*)&h_q[2 * tid]) = hq;
        }
        __syncthreads();

        ull a0 = 0, a1 = 0;
#pragma unroll
        for (int it = 0; it < 32; it++) {
            ulonglong2 hq = *(const ulonglong2*)&h_q[it * 16 + c * 2];
            ffma2(a0, Wq[2 * it + 0], hq.x);
            ffma2(a1, Wq[2 * it + 1], hq.y);
        }
        float sum = sum2(a0) + sum2(a1);
        sum += __shfl_xor_sync(0xFFFFFFFFu, sum, 1);
        sum += __shfl_xor_sync(0xFFFFFFFFu, sum, 2);
        sum += __shfl_xor_sync(0xFFFFFFFFu, sum, 4);
        sum += sGin[t][r][w];

        float vi = __shfl_sync(0xFFFFFFFFu, sum, 0);
        float vf = __shfl_sync(0xFFFFFFFFu, sum, 8);
        float vg = __shfl_sync(0xFFFFFFFFu, sum, 16);
        float vo = __shfl_sync(0xFFFFFFFFu, sum, 24);

        if (lane == 0) {
            float ig = __fdividef(1.f, 1.f + __expf(-vi));
            float fg = __fdividef(1.f, 1.f + __expf(-vf));
            float gg = 1.f - __fdividef(2.f, __expf(2.f * vg) + 1.f);
            float og = __fdividef(1.f, 1.f + __expf(-vo));
            float cn = fg * cc + ig * gg;
            cc = cn;
            float hn = og * (1.f - __fdividef(2.f, __expf(2.f * cn) + 1.f));
            g_h[(t + 1) & 1][u] = hn;
            g_HS[(size_t)t * 1024 + u] = hn;
        }
        __syncthreads();

        if (tid == 0) {
            red_release_add1(&g_arrive);
            const unsigned target = (unsigned)NBLK * (unsigned)(t + 1);
            while (ld_acquire(&g_arrive) < target) {}
        }
        __syncthreads();
    }
}

// ---------------- launch ----------------
extern "C" void kernel_launch(void* const* d_in, const int* in_sizes, int n_in,
                              void* d_out, int out_size) {
    const int* sent = (const int*)d_in[0];
    const float* h0 = (const float*)d_in[1];
    const float* c0 = (const float*)d_in[2];
    const float* emb = (const float*)d_in[3];
    const float* Wih = (const float*)d_in[4];
    const float* Whh = (const float*)d_in[5];
    const float* bih = (const float*)d_in[6];
    const float* bhh = (const float*)d_in[7];
    const float* Wout = (const float*)d_in[8];
    const float* bout = (const float*)d_in[9];
    float* out = (float*)d_out;

    float* gX;
    float* gGin;
    float* gHS;
    unsigned* gAh;
    unsigned* gAl;
    cudaGetSymbolAddress((void**)&gX, g_X);
    cudaGetSymbolAddress((void**)&gGin, g_Gin);
    cudaGetSymbolAddress((void**)&gHS, g_HS);
    cudaGetSymbolAddress((void**)&gAh, g_Ah);
    cudaGetSymbolAddress((void**)&gAl, g_Al);

    // 1) gather inputs + init state + reset barrier
    prep_kernel<<<65, 256>>>(sent, emb, h0);

    // 2) input projection: Gin = X @ W_ih^T + (b_ih + b_hh)
    cvt_split_kernel<<<128, 256>>>(gX);
    gemm_bf16x3<2><<<4096 / 64, 128>>>(gAh, gAl, Wih, gGin, bih, bhh, 4096, 4096);

    // 3) persistent recurrence (register-resident W_hh, counter barrier)
    lstm_persistent<<<NBLK, 256>>>(Whh, gGin, c0);

    // 4) output projection: logits = HS @ W_out^T + b_out
    cvt_split_kernel<<<128, 256>>>(gHS);
    gemm_bf16x3<4><<<(NOUT + 127) / 128, 128>>>(gAh, gAl, Wout, out, bout, nullptr,
                                                NOUT, NOUT);
}

// round 14
// speedup vs baseline: 1.4994x; 1.0391x over previous
#include <cuda_runtime.h>
#include <cuda_bf16.h>
#include <math.h>
#include <stdint.h>

typedef unsigned long long ull;

#define NBLK 128
#define NSTEP 50
#define NOUT 50257

// ---------------- device scratch (no allocs allowed) ----------------
__device__ float g_X[64 * 1024];      // padded inputs (rows 50..63 zero)
__device__ float g_Gin[50 * 4096];    // W_ih @ x_t + b_ih + b_hh
__device__ float g_HS[64 * 1024];     // h_t history (rows 50..63 zero)
__device__ float g_h[2][1024];        // double-buffered hidden state
__device__ unsigned g_arrive;         // cumulative grid-barrier counter
__device__ __align__(16) unsigned g_Ah[64 * 512];  // A bf16-hi pairs (X or HS)
__device__ __align__(16) unsigned g_Al[64 * 512];  // A bf16-lo pairs

// ---------------- helpers ----------------
__device__ __forceinline__ ull pack2(float x, float y) {
    ull r;
    asm("mov.b64 %0, {%1, %2};" : "=l"(r) : "f"(x), "f"(y));
    return r;
}
__device__ __forceinline__ void ffma2(ull& d, ull a, ull b) {
    asm("fma.rn.f32x2 %0, %1, %2, %0;" : "+l"(d) : "l"(a), "l"(b));
}
__device__ __forceinline__ float sum2(ull a) {
    float2 v = *(float2*)&a;
    return v.x + v.y;
}
__device__ __forceinline__ void red_release_add1(unsigned* p) {
    asm volatile("red.release.gpu.global.add.u32 [%0], 1;" :: "l"(p) : "memory");
}
__device__ __forceinline__ unsigned ld_acquire(const unsigned* p) {
    unsigned v;
    asm volatile("ld.acquire.gpu.global.u32 %0, [%1];" : "=r"(v) : "l"(p) : "memory");
    return v;
}
__device__ __forceinline__ uint32_t smem_u32(const void* p) {
    uint32_t a;
    asm("{ .reg .u64 t; cvta.to.shared.u64 t, %1; cvt.u32.u64 %0, t; }"
        : "=r"(a) : "l"(p));
    return a;
}
// ldmatrix x4: four 8x8 b16 tiles (baseline PTX, sm_75+)
__device__ __forceinline__ void ldsm_x4(unsigned& r0, unsigned& r1, unsigned& r2,
                                        unsigned& r3, uint32_t addr) {
    asm volatile(
        "ldmatrix.sync.aligned.m8n8.x4.shared.b16 {%0,%1,%2,%3}, [%4];"
        : "=r"(r0), "=r"(r1), "=r"(r2), "=r"(r3) : "r"(addr));
}

// bf16 hi/lo split of a float pair, packed little-endian (x=low half)
__device__ __forceinline__ void cvt_pair(float x, float y, unsigned& hi, unsigned& lo) {
    __nv_bfloat162 h = __floats2bfloat162_rn(x, y);
    float rx = x - __bfloat162float(h.x);
    float ry = y - __bfloat162float(h.y);
    __nv_bfloat162 l = __floats2bfloat162_rn(rx, ry);
    hi = *(unsigned*)&h;
    lo = *(unsigned*)&l;
}

// mma.sync m16n8k16 bf16 (baseline PTX, works on compute_100)
__device__ __forceinline__ void mma_bf16(float* d, const unsigned* a, const unsigned* b) {
    asm volatile(
        "mma.sync.aligned.m16n8k16.row.col.f32.bf16.bf16.f32 "
        "{%0,%1,%2,%3}, {%4,%5,%6,%7}, {%8,%9}, {%0,%1,%2,%3};"
        : "+f"(d[0]), "+f"(d[1]), "+f"(d[2]), "+f"(d[3])
        : "r"(a[0]), "r"(a[1]), "r"(a[2]), "r"(a[3]), "r"(b[0]), "r"(b[1]));
}

// ---------------- prep: gather X rows, zero pads, init state, reset barrier ----------------
__global__ void prep_kernel(const int* __restrict__ sent,
                            const float* __restrict__ emb,
                            const float* __restrict__ h0) {
    int b = blockIdx.x;
    int tid = threadIdx.x;  // 256 threads, float4 each -> 1024 floats
    if (b < 64) {
        float4* dst = (float4*)(g_X + (size_t)b * 1024);
        if (b < 50) {
            int row = (b == 0) ? 1 : sent[b - 1];  // START_ID = 1
            const float4* src = (const float4*)(emb + (size_t)row * 1024);
            dst[tid] = src[tid];
        } else {
            float4 z = make_float4(0.f, 0.f, 0.f, 0.f);
            dst[tid] = z;
            ((float4*)(g_HS + (size_t)b * 1024))[tid] = z;  // zero MMA pad rows
        }
    } else {
        ((float4*)g_h[0])[tid] = ((const float4*)h0)[tid];
        if (tid == 0) g_arrive = 0u;
    }
}

// ---------------- split a fp32 [64][1024] matrix into packed bf16 hi/lo ----------------
__global__ void cvt_split_kernel(const float* __restrict__ src) {
    int i = blockIdx.x * 256 + threadIdx.x;  // over 32768 float2 pairs
    float2 v = ((const float2*)src)[i];
    unsigned hi, lo;
    cvt_pair(v.x, v.y, hi, lo);
    g_Ah[i] = hi;
    g_Al[i] = lo;
}

// ---------------- bf16x3 tensor-core GEMM: C[m][n] = A[m][:]·W[n][:] + bias ----------------
// EXACT R11 structure (proven 266us) with ONE change: fragment loads via
// ldmatrix.m8n8.x4 instead of scalar LDS (12 ldsm vs 48 LDS per warp-iter).
// A: precomputed hi/lo packed bf16 pairs [64][512]. W: [N][1024] fp32 row-major.
// CTA: BM=64, BN=NT*32, 4 warps; warp = full M x NT*8 N. BK=16 steps, K=1024.
// 3-term bf16 split: D += Ah*Bh + Ah*Bl + Al*Bh.
template <int NT>
__global__ __launch_bounds__(128) void gemm_bf16x3(
    const unsigned* __restrict__ Ah, const unsigned* __restrict__ Al,
    const float* __restrict__ W, float* __restrict__ C,
    const float* __restrict__ bias1, const float* __restrict__ bias2,
    int N, int ldc) {
    constexpr int BN = NT * 32;
    __shared__ unsigned sAh[64][12];
    __shared__ unsigned sAl[64][12];
    __shared__ unsigned sBh[BN][12];
    __shared__ unsigned sBl[BN][12];

    const int tid = threadIdx.x;
    const int wid = tid >> 5;
    const int lane = tid & 31;
    const int l4 = lane >> 2;   // group 0..7
    const int lq = lane & 3;    // thread-in-group
    const int n_block = blockIdx.x * BN;

    float d[4][NT][4];
#pragma unroll
    for (int mt = 0; mt < 4; mt++)
#pragma unroll
        for (int nt = 0; nt < NT; nt++)
#pragma unroll
            for (int q = 0; q < 4; q++) d[mt][nt][q] = 0.f;

    // fill mappings (identical to R11)
    const int ar = tid >> 1;              // A row 0..63
    const int aseg = (tid & 1) * 4;       // word segment {0,4}

    // ldmatrix per-lane byte offsets (row pitch = 12 words = 48B)
    // A x4 tiles (m-low/k-low, m-high/k-low, m-low/k-high, m-high/k-high):
    //   row = mt*16 + (lane&15), word = (lane>>4)*4
    const uint32_t aOff = (uint32_t)((lane & 15) * 48 + (lane >> 4) * 16);
    // B x4 tiles (nt=2p/k-low, nt=2p/k-high, nt=2p+1/k-low, nt=2p+1/k-high):
    //   row = wid*NT*8 + (lane>>4)*8 + (lane&7), word = ((lane>>3)&1)*4
    const uint32_t bOff = (uint32_t)(
        (wid * (NT * 8) + ((lane >> 4) * 8) + (lane & 7)) * 48 +
        ((lane >> 3) & 1) * 16);
    const uint32_t baseAh = smem_u32(&sAh[0][0]);
    const uint32_t baseAl = smem_u32(&sAl[0][0]);
    const uint32_t baseBh = smem_u32(&sBh[0][0]);
    const uint32_t baseBl = smem_u32(&sBl[0][0]);

    // prologue: LDG tile0 -> regs
    uint4 pah = *(const uint4*)(Ah + (size_t)ar * 512 + aseg);
    uint4 pal = *(const uint4*)(Al + (size_t)ar * 512 + aseg);
    float4 pb[NT];
#pragma unroll
    for (int s = 0; s < NT; s++) {
        int i = s * 128 + tid;
        int row = i >> 2, q = i & 3;
        int gn = n_block + row;
        pb[s] = make_float4(0.f, 0.f, 0.f, 0.f);
        if (gn < N) pb[s] = *(const float4*)(W + (size_t)gn * 1024 + q * 4);
    }

    for (int kt = 0; kt < 64; kt++) {
        // ---- STS current tile from prefetch registers ----
        *(uint4*)&sAh[ar][aseg] = pah;
        *(uint4*)&sAl[ar][aseg] = pal;
#pragma unroll
        for (int s = 0; s < NT; s++) {
            int i = s * 128 + tid;
            int row = i >> 2, q = i & 3;
            unsigned h0, l0, h1, l1;
            cvt_pair(pb[s].x, pb[s].y, h0, l0);
            cvt_pair(pb[s].z, pb[s].w, h1, l1);
            sBh[row][q * 2] = h0;
            sBh[row][q * 2 + 1] = h1;
            sBl[row][q * 2] = l0;
            sBl[row][q * 2 + 1] = l1;
        }
        __syncthreads();

        // ---- prefetch next tile (latency hidden under mma) ----
        if (kt + 1 < 64) {
            const int kp = (kt + 1) * 16;
            pah = *(const uint4*)(Ah + (size_t)ar * 512 + (kt + 1) * 8 + aseg);
            pal = *(const uint4*)(Al + (size_t)ar * 512 + (kt + 1) * 8 + aseg);
#pragma unroll
            for (int s = 0; s < NT; s++) {
                int i = s * 128 + tid;
                int row = i >> 2, q = i & 3;
                int gn = n_block + row;
                pb[s] = make_float4(0.f, 0.f, 0.f, 0.f);
                if (gn < N) pb[s] = *(const float4*)(W + (size_t)gn * 1024 + kp + q * 4);
            }
        }

        // ---- fragments via ldmatrix + mma ----
        {
            unsigned bh[NT][2], bl[NT][2];
#pragma unroll
            for (int p = 0; p < NT / 2; p++) {
                uint32_t off = bOff + (uint32_t)(p * 768);  // +16 rows
                ldsm_x4(bh[2 * p][0], bh[2 * p][1], bh[2 * p + 1][0],
                        bh[2 * p + 1][1], baseBh + off);
                ldsm_x4(bl[2 * p][0], bl[2 * p][1], bl[2 * p + 1][0],
                        bl[2 * p + 1][1], baseBl + off);
            }
#pragma unroll
            for (int mt = 0; mt < 4; mt++) {
                uint32_t off = aOff + (uint32_t)(mt * 768);  // +16 rows
                unsigned ah[4], al[4];
                ldsm_x4(ah[0], ah[1], ah[2], ah[3], baseAh + off);
                ldsm_x4(al[0], al[1], al[2], al[3], baseAl + off);
#pragma unroll
                for (int nt = 0; nt < NT; nt++) {
                    mma_bf16(d[mt][nt], ah, bh[nt]);
                    mma_bf16(d[mt][nt], ah, bl[nt]);
                    mma_bf16(d[mt][nt], al, bh[nt]);
                }
            }
        }
        __syncthreads();
    }

    // epilogue: d[mt][nt] -> rows m<50, cols<N, + bias
#pragma unroll
    for (int mt = 0; mt < 4; mt++) {
        int row0 = mt * 16 + l4;
#pragma unroll
        for (int nt = 0; nt < NT; nt++) {
            int col0 = n_block + wid * (NT * 8) + nt * 8 + lq * 2;
#pragma unroll
            for (int half = 0; half < 2; half++) {
                int row = row0 + half * 8;
                if (row < 50) {
                    float* crow = C + (size_t)row * ldc;
                    if (col0 < N) {
                        float bv = bias1[col0] + (bias2 ? bias2[col0] : 0.f);
                        crow[col0] = d[mt][nt][half * 2 + 0] + bv;
                    }
                    if (col0 + 1 < N) {
                        float bv = bias1[col0 + 1] + (bias2 ? bias2[col0 + 1] : 0.f);
                        crow[col0 + 1] = d[mt][nt][half * 2 + 1] + bv;
                    }
                }
            }
        }
    }
}

// ---------------- persistent LSTM (R11-proven, unchanged) ----------------
__global__ __launch_bounds__(256, 1) void lstm_persistent(
    const float* __restrict__ Whh,      // [4096][1024]
    const float* __restrict__ gin_all,  // [50][4096]
    const float* __restrict__ c0) {     // [1024]
    const int b = blockIdx.x;
    const int tid = threadIdx.x;
    const int w = tid >> 5;              // warp -> unit b*8+w
    const int lane = tid & 31;
    const int r = lane >> 3;             // gate 0..3
    const int c = lane & 7;              // chunk 0..7
    const int u = b * 8 + w;
    const int grow = r * 1024 + u;

    __shared__ __align__(16) ull h_q[512];
    __shared__ float sGin[NSTEP][4][8];

    if (tid < 200) {
        int t = tid >> 2, g = tid & 3;
        const float4* src = (const float4*)(gin_all + (size_t)t * 4096 + g * 1024 + b * 8);
        ((float4*)&sGin[t][g][0])[0] = src[0];
        ((float4*)&sGin[t][g][0])[1] = src[1];
    }
    float cc = 0.f;
    if (lane == 0) cc = c0[u];

    ull Wq[64];
    const float4* wp = (const float4*)(Whh + (size_t)grow * 1024);
#pragma unroll
    for (int it = 0; it < 32; it++) {
        float4 w4 = wp[it * 8 + c];
        Wq[2 * it + 0] = pack2(w4.x, w4.y);
        Wq[2 * it + 1] = pack2(w4.z, w4.w);
    }
    __syncthreads();

    for (int t = 0; t < NSTEP; t++) {
        {
            float4 hv = ((const float4*)g_h[t & 1])[tid];
            ulonglong2 hq;
            hq.x = pack2(hv.x, hv.y);
            hq.y = pack2(hv.z, hv.w);
            *((ulonglong2*)&h_q[2 * tid]) = hq;
        }
        __syncthreads();

        ull a0 = 0, a1 = 0;
#pragma unroll
        for (int it = 0; it < 32; it++) {
            ulonglong2 hq = *(const ulonglong2*)&h_q[it * 16 + c * 2];
            ffma2(a0, Wq[2 * it + 0], hq.x);
            ffma2(a1, Wq[2 * it + 1], hq.y);
        }
        float sum = sum2(a0) + sum2(a1);
        sum += __shfl_xor_sync(0xFFFFFFFFu, sum, 1);
        sum += __shfl_xor_sync(0xFFFFFFFFu, sum, 2);
        sum += __shfl_xor_sync(0xFFFFFFFFu, sum, 4);
        sum += sGin[t][r][w];

        float vi = __shfl_sync(0xFFFFFFFFu, sum, 0);
        float vf = __shfl_sync(0xFFFFFFFFu, sum, 8);
        float vg = __shfl_sync(0xFFFFFFFFu, sum, 16);
        float vo = __shfl_sync(0xFFFFFFFFu, sum, 24);

        if (lane == 0) {
            float ig = __fdividef(1.f, 1.f + __expf(-vi));
            float fg = __fdividef(1.f, 1.f + __expf(-vf));
            float gg = 1.f - __fdividef(2.f, __expf(2.f * vg) + 1.f);
            float og = __fdividef(1.f, 1.f + __expf(-vo));
            float cn = fg * cc + ig * gg;
            cc = cn;
            float hn = og * (1.f - __fdividef(2.f, __expf(2.f * cn) + 1.f));
            g_h[(t + 1) & 1][u] = hn;
            g_HS[(size_t)t * 1024 + u] = hn;
        }
        __syncthreads();

        if (tid == 0) {
            red_release_add1(&g_arrive);
            const unsigned target = (unsigned)NBLK * (unsigned)(t + 1);
            while (ld_acquire(&g_arrive) < target) {}
        }
        __syncthreads();
    }
}

// ---------------- launch ----------------
extern "C" void kernel_launch(void* const* d_in, const int* in_sizes, int n_in,
                              void* d_out, int out_size) {
    const int* sent = (const int*)d_in[0];
    const float* h0 = (const float*)d_in[1];
    const float* c0 = (const float*)d_in[2];
    const float* emb = (const float*)d_in[3];
    const float* Wih = (const float*)d_in[4];
    const float* Whh = (const float*)d_in[5];
    const float* bih = (const float*)d_in[6];
    const float* bhh = (const float*)d_in[7];
    const float* Wout = (const float*)d_in[8];
    const float* bout = (const float*)d_in[9];
    float* out = (float*)d_out;

    float* gX;
    float* gGin;
    float* gHS;
    unsigned* gAh;
    unsigned* gAl;
    cudaGetSymbolAddress((void**)&gX, g_X);
    cudaGetSymbolAddress((void**)&gGin, g_Gin);
    cudaGetSymbolAddress((void**)&gHS, g_HS);
    cudaGetSymbolAddress((void**)&gAh, g_Ah);
    cudaGetSymbolAddress((void**)&gAl, g_Al);

    // 1) gather inputs + init state + reset barrier
    prep_kernel<<<65, 256>>>(sent, emb, h0);

    // 2) input projection: Gin = X @ W_ih^T + (b_ih + b_hh)
    cvt_split_kernel<<<128, 256>>>(gX);
    gemm_bf16x3<2><<<4096 / 64, 128>>>(gAh, gAl, Wih, gGin, bih, bhh, 4096, 4096);

    // 3) persistent recurrence (register-resident W_hh, counter barrier)
    lstm_persistent<<<NBLK, 256>>>(Whh, gGin, c0);

    // 4) output projection: logits = HS @ W_out^T + b_out
    cvt_split_kernel<<<128, 256>>>(gHS);
    gemm_bf16x3<4><<<(NOUT + 127) / 128, 128>>>(gAh, gAl, Wout, out, bout, nullptr,
                                                NOUT, NOUT);
}